// round 1
// baseline (speedup 1.0000x reference)
#include <cuda_runtime.h>
#include <math.h>

// Problem constants
#define BB 32
#define TT 32
#define KK 196
#define HH 512
#define AA 512

// Scratch (no cudaMalloc allowed)
__device__ float g_cv[BB * KK * AA];   // 12.8 MB
__device__ float g_cg[BB * TT * AA];   // 2 MB
__device__ float g_cs[BB * TT * AA];   // 2 MB
__device__ float g_zext[BB * TT];

// ---------------------------------------------------------------------------
// accurate-ish tanh: (e^{2x}-1)/(e^{2x}+1) via EX2 + fast division (~1e-6 err)
__device__ __forceinline__ float tanh_fast(float x) {
    float e = exp2f(x * 2.885390081777927f);   // e^{2x}
    return 1.0f - __fdividef(2.0f, e + 1.0f);
}

__device__ __forceinline__ float warp_sum(float v) {
    #pragma unroll
    for (int o = 16; o; o >>= 1) v += __shfl_xor_sync(0xffffffffu, v, o);
    return v;
}

// ---------------------------------------------------------------------------
// Tiled fp32 GEMM: C[M,512] = A[M,512] @ W[512,512], M % 64 == 0
// BM=BN=64, BK=16, 256 threads, 4x4 microtile
__global__ void gemm64(const float* __restrict__ A, const float* __restrict__ W,
                       int which, int M) {
    const int N = 512, KD = 512;
    float* C = (which == 0) ? g_cv : (which == 1) ? g_cg : g_cs;

    __shared__ float As[16][65];   // [k][m], padded
    __shared__ float Bs[16][64];   // [k][n]

    int tid = threadIdx.x;
    int bx = blockIdx.x, by = blockIdx.y;

    int arow = tid >> 2, acol = (tid & 3) << 2;     // A: 64 rows x 16 cols
    int brow = tid >> 4, bcol = (tid & 15) << 2;    // B: 16 rows x 64 cols
    int tx = tid & 15, ty = tid >> 4;

    const float* Ap = A + (by * 64 + arow) * KD + acol;
    const float* Bp = W + brow * N + bx * 64 + bcol;

    float acc[4][4];
    #pragma unroll
    for (int i = 0; i < 4; i++)
        #pragma unroll
        for (int j = 0; j < 4; j++) acc[i][j] = 0.0f;

    for (int k0 = 0; k0 < KD; k0 += 16) {
        float4 av = *(const float4*)(Ap + k0);
        float4 bv = *(const float4*)(Bp + (size_t)k0 * N);
        As[acol + 0][arow] = av.x;
        As[acol + 1][arow] = av.y;
        As[acol + 2][arow] = av.z;
        As[acol + 3][arow] = av.w;
        *(float4*)&Bs[brow][bcol] = bv;
        __syncthreads();

        #pragma unroll
        for (int kk = 0; kk < 16; kk++) {
            float a0 = As[kk][ty * 4 + 0];
            float a1 = As[kk][ty * 4 + 1];
            float a2 = As[kk][ty * 4 + 2];
            float a3 = As[kk][ty * 4 + 3];
            float4 b4 = *(const float4*)&Bs[kk][tx * 4];
            acc[0][0] = fmaf(a0, b4.x, acc[0][0]);
            acc[0][1] = fmaf(a0, b4.y, acc[0][1]);
            acc[0][2] = fmaf(a0, b4.z, acc[0][2]);
            acc[0][3] = fmaf(a0, b4.w, acc[0][3]);
            acc[1][0] = fmaf(a1, b4.x, acc[1][0]);
            acc[1][1] = fmaf(a1, b4.y, acc[1][1]);
            acc[1][2] = fmaf(a1, b4.z, acc[1][2]);
            acc[1][3] = fmaf(a1, b4.w, acc[1][3]);
            acc[2][0] = fmaf(a2, b4.x, acc[2][0]);
            acc[2][1] = fmaf(a2, b4.y, acc[2][1]);
            acc[2][2] = fmaf(a2, b4.z, acc[2][2]);
            acc[2][3] = fmaf(a2, b4.w, acc[2][3]);
            acc[3][0] = fmaf(a3, b4.x, acc[3][0]);
            acc[3][1] = fmaf(a3, b4.y, acc[3][1]);
            acc[3][2] = fmaf(a3, b4.z, acc[3][2]);
            acc[3][3] = fmaf(a3, b4.w, acc[3][3]);
        }
        __syncthreads();
    }

    float* Cp = C + (size_t)(by * 64 + ty * 4) * N + bx * 64 + tx * 4;
    #pragma unroll
    for (int i = 0; i < 4; i++) {
        float4 o = make_float4(acc[i][0], acc[i][1], acc[i][2], acc[i][3]);
        *(float4*)(Cp + (size_t)i * N) = o;
    }
}

// ---------------------------------------------------------------------------
// z_ext[b,t] = sum_a wh[a] * tanh(cs[b,t,a] + cg[b,t,a])
// one warp per row; grid 128 x 256 threads
__global__ void zext_kernel(const float* __restrict__ wh) {
    int wid = threadIdx.x >> 5, lane = threadIdx.x & 31;
    int row = blockIdx.x * 8 + wid;   // < 1024
    const float* cs = g_cs + (size_t)row * AA;
    const float* cg = g_cg + (size_t)row * AA;
    float acc = 0.0f;
    #pragma unroll
    for (int j = 0; j < 16; j++) {
        int a = lane + 32 * j;
        acc = fmaf(wh[a], tanh_fast(cs[a] + cg[a]), acc);
    }
    acc = warp_sum(acc);
    if (lane == 0) g_zext[row] = acc;
}

// ---------------------------------------------------------------------------
// Fused z_t: z[b,t,k] = sum_a wh[a]*tanh(cv[b,k,a] + cg[b,t,a])
// grid (49, 32): block handles b, 4 k's, all 32 t. 256 thr = 8 warps, warp -> 4 t's.
// dyn smem: cg[32][512] + cv[4][512] + wh[512] = 75776 B
__global__ void zfused_kernel(const float* __restrict__ wh, float* __restrict__ zout) {
    extern __shared__ float sm[];
    float* s_cg = sm;              // 16384
    float* s_cv = sm + 16384;      // 2048
    float* s_wh = sm + 18432;      // 512

    int b = blockIdx.y;
    int k0 = blockIdx.x * 4;
    int tid = threadIdx.x;

    const float* cgp = g_cg + (size_t)b * TT * AA;
    const float* cvp = g_cv + ((size_t)b * KK + k0) * AA;

    for (int i = tid * 4; i < 16384; i += 1024)
        *(float4*)&s_cg[i] = *(const float4*)(cgp + i);
    for (int i = tid * 4; i < 2048; i += 1024)
        *(float4*)&s_cv[i] = *(const float4*)(cvp + i);
    if (tid * 4 < 512)
        *(float4*)&s_wh[tid * 4] = *(const float4*)(wh + tid * 4);
    __syncthreads();

    int wid = tid >> 5, lane = tid & 31;
    float whr[16];
    #pragma unroll
    for (int j = 0; j < 16; j++) whr[j] = s_wh[lane + 32 * j];

    #pragma unroll
    for (int i = 0; i < 4; i++) {
        int t = wid * 4 + i;
        const float* cgt = &s_cg[t * 512];
        #pragma unroll
        for (int kk = 0; kk < 4; kk++) {
            const float* cvk = &s_cv[kk * 512];
            float acc = 0.0f;
            #pragma unroll
            for (int j = 0; j < 16; j++) {
                int a = lane + 32 * j;
                acc = fmaf(whr[j], tanh_fast(cvk[a] + cgt[a]), acc);
            }
            acc = warp_sum(acc);
            if (lane == 0)
                zout[((size_t)(b * TT + t)) * KK + k0 + kk] = acc;
        }
    }
}

// ---------------------------------------------------------------------------
// Softmax over K=196 (in-place on z -> alpha) + beta from extended softmax
// one warp per (b,t) row; grid 128 x 256
__global__ void softmax_kernel(float* __restrict__ z, float* __restrict__ beta) {
    const float L2E = 1.4426950408889634f;
    int wid = threadIdx.x >> 5, lane = threadIdx.x & 31;
    int row = blockIdx.x * 8 + wid;   // < 1024
    float* zr = z + (size_t)row * KK;

    float v[7];
    float m = -INFINITY;
    #pragma unroll
    for (int j = 0; j < 7; j++) {
        int k = lane + 32 * j;
        v[j] = (k < KK) ? zr[k] : -INFINITY;
        m = fmaxf(m, v[j]);
    }
    #pragma unroll
    for (int o = 16; o; o >>= 1) m = fmaxf(m, __shfl_xor_sync(0xffffffffu, m, o));

    float s = 0.0f;
    #pragma unroll
    for (int j = 0; j < 7; j++) {
        float e = exp2f((v[j] - m) * L2E);   // -inf -> 0
        v[j] = e;
        s += e;
    }
    s = warp_sum(s);

    float inv = __fdividef(1.0f, s);
    #pragma unroll
    for (int j = 0; j < 7; j++) {
        int k = lane + 32 * j;
        if (k < KK) zr[k] = v[j] * inv;
    }

    if (lane == 0) {
        float ze = g_zext[row];
        float m2 = fmaxf(m, ze);
        float ee = exp2f((ze - m2) * L2E);
        float s2 = s * exp2f((m - m2) * L2E) + ee;
        beta[row] = __fdividef(ee, s2);
    }
}

// ---------------------------------------------------------------------------
// c_hat[b,t,:] = beta*sentinel + (1-beta) * sum_k alpha[b,t,k]*att_feats[b,k,:]
// grid (32 b, 4 tgroups), 256 thr; thread owns 2 h via float2; 8 t per block
__global__ void ct_kernel(const float* __restrict__ af, const float* __restrict__ sent,
                          const float* __restrict__ alpha, const float* __restrict__ beta,
                          float* __restrict__ chat) {
    __shared__ float s_alpha[8][KK];
    __shared__ float s_beta[8];
    int b = blockIdx.x, tg = blockIdx.y;
    int tid = threadIdx.x;
    int trow0 = b * TT + tg * 8;

    for (int i = tid; i < 8 * KK; i += 256)
        s_alpha[i / KK][i % KK] = alpha[(size_t)(trow0 + i / KK) * KK + i % KK];
    if (tid < 8) s_beta[tid] = beta[trow0 + tid];
    __syncthreads();

    float acc[8][2];
    #pragma unroll
    for (int t = 0; t < 8; t++) { acc[t][0] = 0.0f; acc[t][1] = 0.0f; }

    const float* afb = af + (size_t)b * KK * HH;
    int h2 = tid * 2;
    for (int k = 0; k < KK; k++) {
        float2 vv = *(const float2*)(afb + (size_t)k * HH + h2);
        #pragma unroll
        for (int t = 0; t < 8; t++) {
            float al = s_alpha[t][k];
            acc[t][0] = fmaf(al, vv.x, acc[t][0]);
            acc[t][1] = fmaf(al, vv.y, acc[t][1]);
        }
    }

    #pragma unroll
    for (int t = 0; t < 8; t++) {
        float be = s_beta[t];
        float om = 1.0f - be;
        size_t row = (size_t)(trow0 + t);
        float2 sv = *(const float2*)(sent + row * HH + h2);
        float2 o;
        o.x = be * sv.x + om * acc[t][0];
        o.y = be * sv.y + om * acc[t][1];
        *(float2*)(chat + row * HH + h2) = o;
    }
}

// ---------------------------------------------------------------------------
extern "C" void kernel_launch(void* const* d_in, const int* in_sizes, int n_in,
                              void* d_out, int out_size) {
    const float* att  = (const float*)d_in[0];  // (32,196,512)
    const float* hid  = (const float*)d_in[1];  // (32,32,512)
    const float* sent = (const float*)d_in[2];  // (32,32,512)
    const float* Wv   = (const float*)d_in[3];  // (512,512)
    const float* Wg   = (const float*)d_in[4];
    const float* Ws   = (const float*)d_in[5];
    const float* wh   = (const float*)d_in[6];  // (512,)

    float* out   = (float*)d_out;
    float* chat  = out;                               // 524288
    float* alpha = out + (size_t)BB * TT * HH;        // 200704 (z_t written here first)
    float* beta  = alpha + (size_t)BB * TT * KK;      // 1024

    cudaFuncSetAttribute(zfused_kernel,
                         cudaFuncAttributeMaxDynamicSharedMemorySize, 76800);

    // 1-3: GEMMs
    gemm64<<<dim3(8, 98), 256>>>(att,  Wv, 0, BB * KK);   // cv
    gemm64<<<dim3(8, 16), 256>>>(hid,  Wg, 1, BB * TT);   // cg
    gemm64<<<dim3(8, 16), 256>>>(sent, Ws, 2, BB * TT);   // cs

    // 4: z_ext
    zext_kernel<<<128, 256>>>(wh);

    // 5: fused z_t -> alpha region
    zfused_kernel<<<dim3(49, 32), 256, 75776>>>(wh, alpha);

    // 6: softmax (in-place) + beta
    softmax_kernel<<<128, 256>>>(alpha, beta);

    // 7: c_t + sentinel blend
    ct_kernel<<<dim3(32, 4), 256>>>(att, sent, alpha, beta, chat);
}

// round 4
// speedup vs baseline: 1.2626x; 1.2626x over previous
#include <cuda_runtime.h>
#include <cuda_bf16.h>
#include <cstdint>
#include <math.h>

// Problem constants
#define BB 32
#define TT 32
#define KK 196
#define HH 512
#define AA 512
#define GK 512

// ---------------------------------------------------------------------------
// Scratch (__device__ globals; no cudaMalloc allowed)
__device__ float g_cv[BB * KK * AA];               // 12.8 MB
__device__ float g_cg[BB * TT * AA];               // 2 MB
__device__ float g_cs[BB * TT * AA];               // 2 MB
__device__ float g_zext[BB * TT];
__device__ __nv_bfloat16 g_xh[BB * KK * HH];       // activation hi
__device__ __nv_bfloat16 g_xl[BB * KK * HH];       // activation lo
__device__ __nv_bfloat16 g_wh[AA * HH];            // W^T hi  [a][h]
__device__ __nv_bfloat16 g_wl[AA * HH];            // W^T lo

// ---------------------------------------------------------------------------
__device__ __forceinline__ float tanh_mufu(float x) {
    float y;
    asm("tanh.approx.f32 %0, %1;" : "=f"(y) : "f"(x));
    return y;
}
__device__ __forceinline__ float warp_sum(float v) {
    #pragma unroll
    for (int o = 16; o; o >>= 1) v += __shfl_xor_sync(0xffffffffu, v, o);
    return v;
}

// mma.sync m16n8k16 row.col f32.bf16.bf16.f32, D == C (in-place accumulate)
__device__ __forceinline__ void hmma(float* c, const uint32_t* a, const uint32_t* b) {
    asm volatile(
        "mma.sync.aligned.m16n8k16.row.col.f32.bf16.bf16.f32 "
        "{%0,%1,%2,%3}, {%4,%5,%6,%7}, {%8,%9}, {%0,%1,%2,%3};"
        : "+f"(c[0]), "+f"(c[1]), "+f"(c[2]), "+f"(c[3])
        : "r"(a[0]), "r"(a[1]), "r"(a[2]), "r"(a[3]), "r"(b[0]), "r"(b[1]));
}

// ---------------------------------------------------------------------------
// fp32 -> bf16 hi/lo split (vectorized by 4)
__global__ void split_bf16(const float* __restrict__ X, __nv_bfloat16* __restrict__ H,
                           __nv_bfloat16* __restrict__ L, int n4) {
    int i = blockIdx.x * blockDim.x + threadIdx.x;
    if (i >= n4) return;
    float4 v = ((const float4*)X)[i];
    __nv_bfloat16 h0 = __float2bfloat16(v.x);
    __nv_bfloat16 h1 = __float2bfloat16(v.y);
    __nv_bfloat16 h2 = __float2bfloat16(v.z);
    __nv_bfloat16 h3 = __float2bfloat16(v.w);
    __nv_bfloat16 l0 = __float2bfloat16(v.x - __bfloat162float(h0));
    __nv_bfloat16 l1 = __float2bfloat16(v.y - __bfloat162float(h1));
    __nv_bfloat16 l2 = __float2bfloat16(v.z - __bfloat162float(h2));
    __nv_bfloat16 l3 = __float2bfloat16(v.w - __bfloat162float(h3));
    ((__nv_bfloat162*)H)[2 * i]     = __nv_bfloat162(h0, h1);
    ((__nv_bfloat162*)H)[2 * i + 1] = __nv_bfloat162(h2, h3);
    ((__nv_bfloat162*)L)[2 * i]     = __nv_bfloat162(l0, l1);
    ((__nv_bfloat162*)L)[2 * i + 1] = __nv_bfloat162(l2, l3);
}

// W[h][a] -> W^T[a][h], hi/lo split. grid (16,16), block (32,8)
__global__ void wsplit(const float* __restrict__ W, __nv_bfloat16* __restrict__ Ht,
                       __nv_bfloat16* __restrict__ Lt) {
    __shared__ float t[32][33];
    int a0 = blockIdx.x * 32, h0 = blockIdx.y * 32;
    int tx = threadIdx.x, ty = threadIdx.y;
    #pragma unroll
    for (int r = ty; r < 32; r += 8)
        t[r][tx] = W[(size_t)(h0 + r) * AA + a0 + tx];
    __syncthreads();
    #pragma unroll
    for (int r = ty; r < 32; r += 8) {
        float v = t[tx][r];   // = W[h0+tx][a0+r]
        __nv_bfloat16 hh = __float2bfloat16(v);
        Ht[(size_t)(a0 + r) * HH + h0 + tx] = hh;
        Lt[(size_t)(a0 + r) * HH + h0 + tx] = __float2bfloat16(v - __bfloat162float(hh));
    }
}

// ---------------------------------------------------------------------------
// bf16x3 tensor-core GEMM via mma.sync:
//   C[M,512] = X[M,512] @ W  with W^T (K-major) in Bh/Bl.
// Block tile 128x128xBK32, 256 threads = 8 warps (2 x 4), warp tile 64x32.
// Smem rows padded to 40 bf16 (80B) -> conflict-free frag LDS.
#define SROW 40

__global__ void __launch_bounds__(256) mma_gemm(const __nv_bfloat16* __restrict__ Ah,
                                                const __nv_bfloat16* __restrict__ Al,
                                                const __nv_bfloat16* __restrict__ Bhp,
                                                const __nv_bfloat16* __restrict__ Blp,
                                                float* __restrict__ C) {
    __shared__ __nv_bfloat16 sAh[128 * SROW];
    __shared__ __nv_bfloat16 sAl[128 * SROW];
    __shared__ __nv_bfloat16 sBh[128 * SROW];
    __shared__ __nv_bfloat16 sBl[128 * SROW];

    int tid = threadIdx.x, wid = tid >> 5, lane = tid & 31;
    int wm = wid >> 2, wn = wid & 3;            // 2 x 4 warp grid
    int g = lane >> 2, tig = lane & 3;
    int n0 = blockIdx.x * 128, m0 = blockIdx.y * 128;

    float acc[4][4][4];
    #pragma unroll
    for (int i = 0; i < 4; i++)
        #pragma unroll
        for (int j = 0; j < 4; j++)
            #pragma unroll
            for (int q = 0; q < 4; q++) acc[i][j][q] = 0.0f;

    // stage-load mapping: 256 threads, each thread: 2 rows x 16B per array
    int lr = tid >> 2, lc = (tid & 3) * 8;      // row 0..63, col 0/8/16/24

    for (int k0 = 0; k0 < GK; k0 += 32) {
        #pragma unroll
        for (int p = 0; p < 2; p++) {
            int r = lr + 64 * p;
            const size_t ga = (size_t)(m0 + r) * GK + k0 + lc;
            const size_t gb = (size_t)(n0 + r) * HH + k0 + lc;
            *(uint4*)&sAh[r * SROW + lc] = *(const uint4*)&Ah[ga];
            *(uint4*)&sAl[r * SROW + lc] = *(const uint4*)&Al[ga];
            *(uint4*)&sBh[r * SROW + lc] = *(const uint4*)&Bhp[gb];
            *(uint4*)&sBl[r * SROW + lc] = *(const uint4*)&Blp[gb];
        }
        __syncthreads();

        #pragma unroll
        for (int ks = 0; ks < 2; ks++) {
            int kk = ks * 16;
            uint32_t aH[4][4], aL[4][4], bH[4][2], bL[4][2];
            #pragma unroll
            for (int mf = 0; mf < 4; mf++) {
                int mr = wm * 64 + mf * 16;
                int c0 = kk + 2 * tig;
                aH[mf][0] = *(const uint32_t*)&sAh[(mr + g) * SROW + c0];
                aH[mf][1] = *(const uint32_t*)&sAh[(mr + g + 8) * SROW + c0];
                aH[mf][2] = *(const uint32_t*)&sAh[(mr + g) * SROW + c0 + 8];
                aH[mf][3] = *(const uint32_t*)&sAh[(mr + g + 8) * SROW + c0 + 8];
                aL[mf][0] = *(const uint32_t*)&sAl[(mr + g) * SROW + c0];
                aL[mf][1] = *(const uint32_t*)&sAl[(mr + g + 8) * SROW + c0];
                aL[mf][2] = *(const uint32_t*)&sAl[(mr + g) * SROW + c0 + 8];
                aL[mf][3] = *(const uint32_t*)&sAl[(mr + g + 8) * SROW + c0 + 8];
            }
            #pragma unroll
            for (int nf = 0; nf < 4; nf++) {
                int nr = wn * 32 + nf * 8;
                int c0 = kk + 2 * tig;
                bH[nf][0] = *(const uint32_t*)&sBh[(nr + g) * SROW + c0];
                bH[nf][1] = *(const uint32_t*)&sBh[(nr + g) * SROW + c0 + 8];
                bL[nf][0] = *(const uint32_t*)&sBl[(nr + g) * SROW + c0];
                bL[nf][1] = *(const uint32_t*)&sBl[(nr + g) * SROW + c0 + 8];
            }
            #pragma unroll
            for (int mf = 0; mf < 4; mf++)
                #pragma unroll
                for (int nf = 0; nf < 4; nf++) hmma(acc[mf][nf], aH[mf], bH[nf]);
            #pragma unroll
            for (int mf = 0; mf < 4; mf++)
                #pragma unroll
                for (int nf = 0; nf < 4; nf++) hmma(acc[mf][nf], aH[mf], bL[nf]);
            #pragma unroll
            for (int mf = 0; mf < 4; mf++)
                #pragma unroll
                for (int nf = 0; nf < 4; nf++) hmma(acc[mf][nf], aL[mf], bH[nf]);
        }
        __syncthreads();
    }

    // epilogue
    #pragma unroll
    for (int mf = 0; mf < 4; mf++) {
        int row = m0 + wm * 64 + mf * 16 + g;
        #pragma unroll
        for (int nf = 0; nf < 4; nf++) {
            int col = n0 + wn * 32 + nf * 8 + 2 * tig;
            *(float2*)&C[(size_t)row * AA + col] =
                make_float2(acc[mf][nf][0], acc[mf][nf][1]);
            *(float2*)&C[(size_t)(row + 8) * AA + col] =
                make_float2(acc[mf][nf][2], acc[mf][nf][3]);
        }
    }
}

// ---------------------------------------------------------------------------
// z_ext[b,t] = sum_a wh[a] * tanh(cs[b,t,a] + cg[b,t,a]); one warp per row
__global__ void zext_kernel(const float* __restrict__ wh) {
    int wid = threadIdx.x >> 5, lane = threadIdx.x & 31;
    int row = blockIdx.x * 8 + wid;
    const float* cs = g_cs + (size_t)row * AA;
    const float* cg = g_cg + (size_t)row * AA;
    float acc = 0.0f;
    #pragma unroll
    for (int j = 0; j < 16; j++) {
        int a = lane + 32 * j;
        acc = fmaf(wh[a], tanh_mufu(cs[a] + cg[a]), acc);
    }
    acc = warp_sum(acc);
    if (lane == 0) g_zext[row] = acc;
}

// ---------------------------------------------------------------------------
// Fused z_t: z[b,t,k] = sum_a wh[a]*tanh(cv[b,k,a] + cg[b,t,a])
__global__ void zfused_kernel(const float* __restrict__ wh, float* __restrict__ zout) {
    extern __shared__ float sm[];
    float* s_cg = sm;              // 16384 floats
    float* s_cv = sm + 16384;      // 2048
    float* s_wh = sm + 18432;      // 512

    int b = blockIdx.y;
    int k0 = blockIdx.x * 4;
    int tid = threadIdx.x;

    const float* cgp = g_cg + (size_t)b * TT * AA;
    const float* cvp = g_cv + ((size_t)b * KK + k0) * AA;

    for (int i = tid * 4; i < 16384; i += 1024)
        *(float4*)&s_cg[i] = *(const float4*)(cgp + i);
    for (int i = tid * 4; i < 2048; i += 1024)
        *(float4*)&s_cv[i] = *(const float4*)(cvp + i);
    if (tid * 4 < 512)
        *(float4*)&s_wh[tid * 4] = *(const float4*)(wh + tid * 4);
    __syncthreads();

    int wid = tid >> 5, lane = tid & 31;
    float whr[16];
    #pragma unroll
    for (int j = 0; j < 16; j++) whr[j] = s_wh[lane + 32 * j];

    #pragma unroll
    for (int i = 0; i < 4; i++) {
        int t = wid * 4 + i;
        const float* cgt = &s_cg[t * 512];
        #pragma unroll
        for (int kk = 0; kk < 4; kk++) {
            const float* cvk = &s_cv[kk * 512];
            float acc = 0.0f;
            #pragma unroll
            for (int j = 0; j < 16; j++) {
                int a = lane + 32 * j;
                acc = fmaf(whr[j], tanh_mufu(cvk[a] + cgt[a]), acc);
            }
            acc = warp_sum(acc);
            if (lane == 0)
                zout[((size_t)(b * TT + t)) * KK + k0 + kk] = acc;
        }
    }
}

// ---------------------------------------------------------------------------
// Softmax over K=196 + beta; one warp per (b,t) row
__global__ void softmax_kernel(float* __restrict__ z, float* __restrict__ beta) {
    const float L2E = 1.4426950408889634f;
    int wid = threadIdx.x >> 5, lane = threadIdx.x & 31;
    int row = blockIdx.x * 8 + wid;
    float* zr = z + (size_t)row * KK;

    float v[7];
    float m = -INFINITY;
    #pragma unroll
    for (int j = 0; j < 7; j++) {
        int k = lane + 32 * j;
        v[j] = (k < KK) ? zr[k] : -INFINITY;
        m = fmaxf(m, v[j]);
    }
    #pragma unroll
    for (int o = 16; o; o >>= 1) m = fmaxf(m, __shfl_xor_sync(0xffffffffu, m, o));

    float s = 0.0f;
    #pragma unroll
    for (int j = 0; j < 7; j++) {
        float e = exp2f((v[j] - m) * L2E);
        v[j] = e;
        s += e;
    }
    s = warp_sum(s);

    float inv = __fdividef(1.0f, s);
    #pragma unroll
    for (int j = 0; j < 7; j++) {
        int k = lane + 32 * j;
        if (k < KK) zr[k] = v[j] * inv;
    }

    if (lane == 0) {
        float ze = g_zext[row];
        float m2 = fmaxf(m, ze);
        float ee = exp2f((ze - m2) * L2E);
        float s2 = s * exp2f((m - m2) * L2E) + ee;
        beta[row] = __fdividef(ee, s2);
    }
}

// ---------------------------------------------------------------------------
// c_hat[b,t,:] = beta*sentinel + (1-beta) * sum_k alpha[b,t,k]*att_feats[b,k,:]
__global__ void ct_kernel(const float* __restrict__ af, const float* __restrict__ sent,
                          const float* __restrict__ alpha, const float* __restrict__ beta,
                          float* __restrict__ chat) {
    __shared__ float s_alpha[8][KK];
    __shared__ float s_beta[8];
    int b = blockIdx.x, tg = blockIdx.y;
    int tid = threadIdx.x;
    int trow0 = b * TT + tg * 8;

    for (int i = tid; i < 8 * KK; i += 256)
        s_alpha[i / KK][i % KK] = alpha[(size_t)(trow0 + i / KK) * KK + i % KK];
    if (tid < 8) s_beta[tid] = beta[trow0 + tid];
    __syncthreads();

    float acc[8][2];
    #pragma unroll
    for (int t = 0; t < 8; t++) { acc[t][0] = 0.0f; acc[t][1] = 0.0f; }

    const float* afb = af + (size_t)b * KK * HH;
    int h2 = tid * 2;
    for (int k = 0; k < KK; k++) {
        float2 vv = *(const float2*)(afb + (size_t)k * HH + h2);
        #pragma unroll
        for (int t = 0; t < 8; t++) {
            float al = s_alpha[t][k];
            acc[t][0] = fmaf(al, vv.x, acc[t][0]);
            acc[t][1] = fmaf(al, vv.y, acc[t][1]);
        }
    }

    #pragma unroll
    for (int t = 0; t < 8; t++) {
        float be = s_beta[t];
        float om = 1.0f - be;
        size_t row = (size_t)(trow0 + t);
        float2 sv = *(const float2*)(sent + row * HH + h2);
        float2 o;
        o.x = be * sv.x + om * acc[t][0];
        o.y = be * sv.y + om * acc[t][1];
        *(float2*)(chat + row * HH + h2) = o;
    }
}

// ---------------------------------------------------------------------------
extern "C" void kernel_launch(void* const* d_in, const int* in_sizes, int n_in,
                              void* d_out, int out_size) {
    const float* att  = (const float*)d_in[0];  // (32,196,512)
    const float* hid  = (const float*)d_in[1];  // (32,32,512)
    const float* sent = (const float*)d_in[2];  // (32,32,512)
    const float* Wv   = (const float*)d_in[3];  // (512,512)
    const float* Wg   = (const float*)d_in[4];
    const float* Ws   = (const float*)d_in[5];
    const float* wh   = (const float*)d_in[6];  // (512,)

    float* out   = (float*)d_out;
    float* chat  = out;                               // 524288
    float* alpha = out + (size_t)BB * TT * HH;        // 200704 (z_t staged here)
    float* beta  = alpha + (size_t)BB * TT * KK;      // 1024

    // Resolve __device__ symbols to REAL device pointers (host shadow addresses
    // are invalid as kernel args — round-3 bug).
    __nv_bfloat16 *xh, *xl, *whp, *wlp;
    float *cv, *cg, *cs;
    cudaGetSymbolAddress((void**)&xh,  g_xh);
    cudaGetSymbolAddress((void**)&xl,  g_xl);
    cudaGetSymbolAddress((void**)&whp, g_wh);
    cudaGetSymbolAddress((void**)&wlp, g_wl);
    cudaGetSymbolAddress((void**)&cv,  g_cv);
    cudaGetSymbolAddress((void**)&cg,  g_cg);
    cudaGetSymbolAddress((void**)&cs,  g_cs);
    cudaFuncSetAttribute(zfused_kernel, cudaFuncAttributeMaxDynamicSharedMemorySize, 76800);

    // cv = att @ Wv
    split_bf16<<<3136, 256>>>(att, xh, xl, BB * KK * HH / 4);
    wsplit<<<dim3(16, 16), dim3(32, 8)>>>(Wv, whp, wlp);
    mma_gemm<<<dim3(4, 49), 256>>>(xh, xl, whp, wlp, cv);

    // cg = hid @ Wg
    split_bf16<<<512, 256>>>(hid, xh, xl, BB * TT * HH / 4);
    wsplit<<<dim3(16, 16), dim3(32, 8)>>>(Wg, whp, wlp);
    mma_gemm<<<dim3(4, 8), 256>>>(xh, xl, whp, wlp, cg);

    // cs = sent @ Ws
    split_bf16<<<512, 256>>>(sent, xh, xl, BB * TT * HH / 4);
    wsplit<<<dim3(16, 16), dim3(32, 8)>>>(Ws, whp, wlp);
    mma_gemm<<<dim3(4, 8), 256>>>(xh, xl, whp, wlp, cs);

    // z_ext, fused z_t, softmax, blend
    zext_kernel<<<128, 256>>>(wh);
    zfused_kernel<<<dim3(49, 32), 256, 75776>>>(wh, alpha);
    softmax_kernel<<<128, 256>>>(alpha, beta);
    ct_kernel<<<dim3(32, 4), 256>>>(att, sent, alpha, beta, chat);
}

// round 5
// speedup vs baseline: 1.5089x; 1.1951x over previous
#include <cuda_runtime.h>
#include <cuda_bf16.h>
#include <cstdint>
#include <math.h>

// Problem constants
#define BB 32
#define TT 32
#define KK 196
#define HH 512
#define AA 512
#define GK 512

#define ROWS_ATT (BB * KK)          // 6272
#define ROWS_HID (BB * TT)          // 1024
#define ROWS_ALL (ROWS_ATT + 2 * ROWS_HID)   // 8320

// ---------------------------------------------------------------------------
// Scratch (__device__ globals; no cudaMalloc allowed)
__device__ float g_cv[BB * KK * AA];                 // 12.8 MB
__device__ float g_cg[BB * TT * AA];                 // 2 MB
__device__ float g_cs[BB * TT * AA];                 // 2 MB
__device__ float g_zext[BB * TT];
__device__ __nv_bfloat16 g_xh[ROWS_ALL * HH];        // concat activations hi
__device__ __nv_bfloat16 g_xl[ROWS_ALL * HH];        // concat activations lo
__device__ __nv_bfloat16 g_wh[3 * AA * HH];          // W^T hi (Wv, Wg, Ws)
__device__ __nv_bfloat16 g_wl[3 * AA * HH];          // W^T lo

// ---------------------------------------------------------------------------
__device__ __forceinline__ float tanh_mufu(float x) {
    float y;
    asm("tanh.approx.f32 %0, %1;" : "=f"(y) : "f"(x));
    return y;
}
__device__ __forceinline__ float warp_sum(float v) {
    #pragma unroll
    for (int o = 16; o; o >>= 1) v += __shfl_xor_sync(0xffffffffu, v, o);
    return v;
}

// mma.sync m16n8k16 row.col f32.bf16.bf16.f32, D == C
__device__ __forceinline__ void hmma(float* c, const uint32_t* a, const uint32_t* b) {
    asm volatile(
        "mma.sync.aligned.m16n8k16.row.col.f32.bf16.bf16.f32 "
        "{%0,%1,%2,%3}, {%4,%5,%6,%7}, {%8,%9}, {%0,%1,%2,%3};"
        : "+f"(c[0]), "+f"(c[1]), "+f"(c[2]), "+f"(c[3])
        : "r"(a[0]), "r"(a[1]), "r"(a[2]), "r"(a[3]), "r"(b[0]), "r"(b[1]));
}

__device__ __forceinline__ uint32_t smem_u32(const void* p) {
    uint32_t a;
    asm("{ .reg .u64 t; cvta.to.shared.u64 t, %1; cvt.u32.u64 %0, t; }" : "=r"(a) : "l"(p));
    return a;
}
__device__ __forceinline__ void cp16(uint32_t dst, const void* src) {
    asm volatile("cp.async.cg.shared.global [%0], [%1], 16;" :: "r"(dst), "l"(src));
}
#define CP_COMMIT() asm volatile("cp.async.commit_group;" ::: "memory")
#define CP_WAIT1()  asm volatile("cp.async.wait_group 1;" ::: "memory")
#define CP_WAIT0()  asm volatile("cp.async.wait_group 0;" ::: "memory")

// ---------------------------------------------------------------------------
// fp32 -> bf16 hi/lo split; all three activations in one launch.
// i indexes float4 over the CONCATENATED [att; hid; sent] row space.
__global__ void split_all(const float* __restrict__ att, const float* __restrict__ hid,
                          const float* __restrict__ sent,
                          __nv_bfloat16* __restrict__ H, __nv_bfloat16* __restrict__ L) {
    const int N4 = ROWS_ALL * HH / 4;
    int i = blockIdx.x * blockDim.x + threadIdx.x;
    if (i >= N4) return;
    const float4* src;
    int li;
    if (i < ROWS_ATT * 128)            { src = (const float4*)att;  li = i; }
    else if (i < (ROWS_ATT + ROWS_HID) * 128) { src = (const float4*)hid;  li = i - ROWS_ATT * 128; }
    else                               { src = (const float4*)sent; li = i - (ROWS_ATT + ROWS_HID) * 128; }
    float4 v = src[li];
    __nv_bfloat16 h0 = __float2bfloat16(v.x);
    __nv_bfloat16 h1 = __float2bfloat16(v.y);
    __nv_bfloat16 h2 = __float2bfloat16(v.z);
    __nv_bfloat16 h3 = __float2bfloat16(v.w);
    ((__nv_bfloat162*)H)[2 * i]     = __nv_bfloat162(h0, h1);
    ((__nv_bfloat162*)H)[2 * i + 1] = __nv_bfloat162(h2, h3);
    ((__nv_bfloat162*)L)[2 * i]     = __nv_bfloat162(__float2bfloat16(v.x - __bfloat162float(h0)),
                                                     __float2bfloat16(v.y - __bfloat162float(h1)));
    ((__nv_bfloat162*)L)[2 * i + 1] = __nv_bfloat162(__float2bfloat16(v.z - __bfloat162float(h2)),
                                                     __float2bfloat16(v.w - __bfloat162float(h3)));
}

// W[h][a] -> W^T[a][h], hi/lo split, 3 weights via blockIdx.z
__global__ void wsplit_all(const float* __restrict__ Wv, const float* __restrict__ Wg,
                           const float* __restrict__ Ws,
                           __nv_bfloat16* __restrict__ Ht, __nv_bfloat16* __restrict__ Lt) {
    __shared__ float t[32][33];
    int z = blockIdx.z;
    const float* W = (z == 0) ? Wv : (z == 1) ? Wg : Ws;
    size_t wo = (size_t)z * AA * HH;
    int a0 = blockIdx.x * 32, h0 = blockIdx.y * 32;
    int tx = threadIdx.x, ty = threadIdx.y;
    #pragma unroll
    for (int r = ty; r < 32; r += 8)
        t[r][tx] = W[(size_t)(h0 + r) * AA + a0 + tx];
    __syncthreads();
    #pragma unroll
    for (int r = ty; r < 32; r += 8) {
        float v = t[tx][r];
        __nv_bfloat16 hh = __float2bfloat16(v);
        Ht[wo + (size_t)(a0 + r) * HH + h0 + tx] = hh;
        Lt[wo + (size_t)(a0 + r) * HH + h0 + tx] = __float2bfloat16(v - __bfloat162float(hh));
    }
}

// ---------------------------------------------------------------------------
// Merged bf16x3 tensor GEMM, cp.async 2-stage pipeline.
// grid (4, 65): my<49 -> cv, my<57 -> cg, else cs.
// Block 128x128xBK32, 256 thr, warp tile 64x32. SROW=40 pad (conflict-free).
#define SROW 40
#define TILE_E (128 * SROW)              // elements per tile
#define TILE_B (TILE_E * 2)              // 10240 bytes
#define MMA_DSMEM (TILE_B * 4 * 2)       // 4 arrays x 2 stages = 81920

__global__ void __launch_bounds__(256) mma_gemm_all(
        const __nv_bfloat16* __restrict__ Xh, const __nv_bfloat16* __restrict__ Xl,
        const __nv_bfloat16* __restrict__ Wh, const __nv_bfloat16* __restrict__ Wl,
        float* __restrict__ cv, float* __restrict__ cg, float* __restrict__ cs) {
    extern __shared__ __nv_bfloat16 dynsm[];
    uint32_t sb = smem_u32(dynsm);

    int tid = threadIdx.x, wid = tid >> 5, lane = tid & 31;
    int wm = wid >> 2, wn = wid & 3;
    int g = lane >> 2, tig = lane & 3;
    int my = blockIdx.y;
    int n0 = blockIdx.x * 128;

    int arow0; size_t wo; float* C; int crow0;
    if (my < 49)      { arow0 = my * 128;                    wo = 0;                      C = cv; crow0 = my * 128; }
    else if (my < 57) { arow0 = ROWS_ATT + (my - 49) * 128;  wo = (size_t)AA * HH;        C = cg; crow0 = (my - 49) * 128; }
    else              { arow0 = ROWS_ATT + ROWS_HID + (my - 57) * 128; wo = 2 * (size_t)AA * HH; C = cs; crow0 = (my - 57) * 128; }

    float acc[4][4][4];
    #pragma unroll
    for (int i = 0; i < 4; i++)
        #pragma unroll
        for (int j = 0; j < 4; j++)
            #pragma unroll
            for (int q = 0; q < 4; q++) acc[i][j][q] = 0.0f;

    int lr = tid >> 2, lc = (tid & 3) * 8;   // row 0..63, col 0/8/16/24

    // stage s, array a (0=Ah,1=Al,2=Bh,3=Bl): base byte = (s*4+a)*TILE_B
    auto load_stage = [&](int s, int k0) {
        uint32_t base = sb + (uint32_t)(s * 4) * TILE_B;
        #pragma unroll
        for (int p = 0; p < 2; p++) {
            int r = lr + 64 * p;
            uint32_t soff = (uint32_t)(r * SROW + lc) * 2;
            const __nv_bfloat16* gA  = Xh + (size_t)(arow0 + r) * GK + k0 + lc;
            const __nv_bfloat16* gAl = Xl + (size_t)(arow0 + r) * GK + k0 + lc;
            const __nv_bfloat16* gB  = Wh + wo + (size_t)(n0 + r) * HH + k0 + lc;
            const __nv_bfloat16* gBl = Wl + wo + (size_t)(n0 + r) * HH + k0 + lc;
            cp16(base + 0 * TILE_B + soff, gA);
            cp16(base + 1 * TILE_B + soff, gAl);
            cp16(base + 2 * TILE_B + soff, gB);
            cp16(base + 3 * TILE_B + soff, gBl);
        }
    };

    load_stage(0, 0);
    CP_COMMIT();

    const int NIT = GK / 32;   // 16
    for (int it = 0; it < NIT; it++) {
        if (it + 1 < NIT) {
            load_stage((it + 1) & 1, (it + 1) * 32);
            CP_COMMIT();
            CP_WAIT1();
        } else {
            CP_WAIT0();
        }
        __syncthreads();

        const __nv_bfloat16* sAh = dynsm + (size_t)((it & 1) * 4 + 0) * TILE_E;
        const __nv_bfloat16* sAl = dynsm + (size_t)((it & 1) * 4 + 1) * TILE_E;
        const __nv_bfloat16* sBh = dynsm + (size_t)((it & 1) * 4 + 2) * TILE_E;
        const __nv_bfloat16* sBl = dynsm + (size_t)((it & 1) * 4 + 3) * TILE_E;

        #pragma unroll
        for (int ks = 0; ks < 2; ks++) {
            int c0 = ks * 16 + 2 * tig;
            uint32_t aH[4][4], aL[4][4], bH[4][2], bL[4][2];
            #pragma unroll
            for (int mf = 0; mf < 4; mf++) {
                int mr = wm * 64 + mf * 16;
                aH[mf][0] = *(const uint32_t*)&sAh[(mr + g) * SROW + c0];
                aH[mf][1] = *(const uint32_t*)&sAh[(mr + g + 8) * SROW + c0];
                aH[mf][2] = *(const uint32_t*)&sAh[(mr + g) * SROW + c0 + 8];
                aH[mf][3] = *(const uint32_t*)&sAh[(mr + g + 8) * SROW + c0 + 8];
                aL[mf][0] = *(const uint32_t*)&sAl[(mr + g) * SROW + c0];
                aL[mf][1] = *(const uint32_t*)&sAl[(mr + g + 8) * SROW + c0];
                aL[mf][2] = *(const uint32_t*)&sAl[(mr + g) * SROW + c0 + 8];
                aL[mf][3] = *(const uint32_t*)&sAl[(mr + g + 8) * SROW + c0 + 8];
            }
            #pragma unroll
            for (int nf = 0; nf < 4; nf++) {
                int nr = wn * 32 + nf * 8;
                bH[nf][0] = *(const uint32_t*)&sBh[(nr + g) * SROW + c0];
                bH[nf][1] = *(const uint32_t*)&sBh[(nr + g) * SROW + c0 + 8];
                bL[nf][0] = *(const uint32_t*)&sBl[(nr + g) * SROW + c0];
                bL[nf][1] = *(const uint32_t*)&sBl[(nr + g) * SROW + c0 + 8];
            }
            #pragma unroll
            for (int mf = 0; mf < 4; mf++)
                #pragma unroll
                for (int nf = 0; nf < 4; nf++) hmma(acc[mf][nf], aH[mf], bH[nf]);
            #pragma unroll
            for (int mf = 0; mf < 4; mf++)
                #pragma unroll
                for (int nf = 0; nf < 4; nf++) hmma(acc[mf][nf], aH[mf], bL[nf]);
            #pragma unroll
            for (int mf = 0; mf < 4; mf++)
                #pragma unroll
                for (int nf = 0; nf < 4; nf++) hmma(acc[mf][nf], aL[mf], bH[nf]);
        }
        __syncthreads();
    }

    #pragma unroll
    for (int mf = 0; mf < 4; mf++) {
        int row = crow0 + wm * 64 + mf * 16 + g;
        #pragma unroll
        for (int nf = 0; nf < 4; nf++) {
            int col = n0 + wn * 32 + nf * 8 + 2 * tig;
            *(float2*)&C[(size_t)row * AA + col] =
                make_float2(acc[mf][nf][0], acc[mf][nf][1]);
            *(float2*)&C[(size_t)(row + 8) * AA + col] =
                make_float2(acc[mf][nf][2], acc[mf][nf][3]);
        }
    }
}

// ---------------------------------------------------------------------------
// Fused z_t (+ z_ext on the k0==0 blocks):
//   z[b,t,k] = sum_a wh[a]*tanh(cv[b,k,a] + cg[b,t,a])
//   zext[b,t] = sum_a wh[a]*tanh(cs[b,t,a] + cg[b,t,a])
__global__ void zfused_kernel(const float* __restrict__ wh, float* __restrict__ zout) {
    extern __shared__ float sm[];
    float* s_cg = sm;              // 16384 floats
    float* s_cv = sm + 16384;      // 2048
    float* s_wh = sm + 18432;      // 512

    int b = blockIdx.y;
    int k0 = blockIdx.x * 4;
    int tid = threadIdx.x;

    const float* cgp = g_cg + (size_t)b * TT * AA;
    const float* cvp = g_cv + ((size_t)b * KK + k0) * AA;

    for (int i = tid * 4; i < 16384; i += 1024)
        *(float4*)&s_cg[i] = *(const float4*)(cgp + i);
    for (int i = tid * 4; i < 2048; i += 1024)
        *(float4*)&s_cv[i] = *(const float4*)(cvp + i);
    if (tid * 4 < 512)
        *(float4*)&s_wh[tid * 4] = *(const float4*)(wh + tid * 4);
    __syncthreads();

    int wid = tid >> 5, lane = tid & 31;
    float whr[16];
    #pragma unroll
    for (int j = 0; j < 16; j++) whr[j] = s_wh[lane + 32 * j];

    #pragma unroll
    for (int i = 0; i < 4; i++) {
        int t = wid * 4 + i;
        const float* cgt = &s_cg[t * 512];
        #pragma unroll
        for (int kk = 0; kk < 4; kk++) {
            const float* cvk = &s_cv[kk * 512];
            float acc = 0.0f;
            #pragma unroll
            for (int j = 0; j < 16; j++) {
                int a = lane + 32 * j;
                acc = fmaf(whr[j], tanh_mufu(cvk[a] + cgt[a]), acc);
            }
            acc = warp_sum(acc);
            if (lane == 0)
                zout[((size_t)(b * TT + t)) * KK + k0 + kk] = acc;
        }
    }

    // sentinel row (once per b, on the k0==0 blocks)
    if (blockIdx.x == 0) {
        #pragma unroll
        for (int i = 0; i < 4; i++) {
            int t = wid * 4 + i;
            const float* cst = g_cs + ((size_t)(b * TT + t)) * AA;
            const float* cgt = &s_cg[t * 512];
            float acc = 0.0f;
            #pragma unroll
            for (int j = 0; j < 16; j++) {
                int a = lane + 32 * j;
                acc = fmaf(whr[j], tanh_mufu(cst[a] + cgt[a]), acc);
            }
            acc = warp_sum(acc);
            if (lane == 0) g_zext[b * TT + t] = acc;
        }
    }
}

// ---------------------------------------------------------------------------
// Softmax over K=196 + beta; one warp per (b,t) row
__global__ void softmax_kernel(float* __restrict__ z, float* __restrict__ beta) {
    const float L2E = 1.4426950408889634f;
    int wid = threadIdx.x >> 5, lane = threadIdx.x & 31;
    int row = blockIdx.x * 8 + wid;
    float* zr = z + (size_t)row * KK;

    float v[7];
    float m = -INFINITY;
    #pragma unroll
    for (int j = 0; j < 7; j++) {
        int k = lane + 32 * j;
        v[j] = (k < KK) ? zr[k] : -INFINITY;
        m = fmaxf(m, v[j]);
    }
    #pragma unroll
    for (int o = 16; o; o >>= 1) m = fmaxf(m, __shfl_xor_sync(0xffffffffu, m, o));

    float s = 0.0f;
    #pragma unroll
    for (int j = 0; j < 7; j++) {
        float e = exp2f((v[j] - m) * L2E);
        v[j] = e;
        s += e;
    }
    s = warp_sum(s);

    float inv = __fdividef(1.0f, s);
    #pragma unroll
    for (int j = 0; j < 7; j++) {
        int k = lane + 32 * j;
        if (k < KK) zr[k] = v[j] * inv;
    }

    if (lane == 0) {
        float ze = g_zext[row];
        float m2 = fmaxf(m, ze);
        float ee = exp2f((ze - m2) * L2E);
        float s2 = s * exp2f((m - m2) * L2E) + ee;
        beta[row] = __fdividef(ee, s2);
    }
}

// ---------------------------------------------------------------------------
// c_hat[b,t,:] = beta*sentinel + (1-beta) * sum_k alpha[b,t,k]*att_feats[b,k,:]
__global__ void ct_kernel(const float* __restrict__ af, const float* __restrict__ sent,
                          const float* __restrict__ alpha, const float* __restrict__ beta,
                          float* __restrict__ chat) {
    __shared__ float s_alpha[8][KK];
    __shared__ float s_beta[8];
    int b = blockIdx.x, tg = blockIdx.y;
    int tid = threadIdx.x;
    int trow0 = b * TT + tg * 8;

    for (int i = tid; i < 8 * KK; i += 256)
        s_alpha[i / KK][i % KK] = alpha[(size_t)(trow0 + i / KK) * KK + i % KK];
    if (tid < 8) s_beta[tid] = beta[trow0 + tid];
    __syncthreads();

    float acc[8][2];
    #pragma unroll
    for (int t = 0; t < 8; t++) { acc[t][0] = 0.0f; acc[t][1] = 0.0f; }

    const float* afb = af + (size_t)b * KK * HH;
    int h2 = tid * 2;
    for (int k = 0; k < KK; k++) {
        float2 vv = *(const float2*)(afb + (size_t)k * HH + h2);
        #pragma unroll
        for (int t = 0; t < 8; t++) {
            float al = s_alpha[t][k];
            acc[t][0] = fmaf(al, vv.x, acc[t][0]);
            acc[t][1] = fmaf(al, vv.y, acc[t][1]);
        }
    }

    #pragma unroll
    for (int t = 0; t < 8; t++) {
        float be = s_beta[t];
        float om = 1.0f - be;
        size_t row = (size_t)(trow0 + t);
        float2 sv = *(const float2*)(sent + row * HH + h2);
        float2 o;
        o.x = be * sv.x + om * acc[t][0];
        o.y = be * sv.y + om * acc[t][1];
        *(float2*)(chat + row * HH + h2) = o;
    }
}

// ---------------------------------------------------------------------------
extern "C" void kernel_launch(void* const* d_in, const int* in_sizes, int n_in,
                              void* d_out, int out_size) {
    const float* att  = (const float*)d_in[0];
    const float* hid  = (const float*)d_in[1];
    const float* sent = (const float*)d_in[2];
    const float* Wv   = (const float*)d_in[3];
    const float* Wg   = (const float*)d_in[4];
    const float* Ws   = (const float*)d_in[5];
    const float* wh   = (const float*)d_in[6];

    float* out   = (float*)d_out;
    float* chat  = out;                               // 524288
    float* alpha = out + (size_t)BB * TT * HH;        // 200704 (z_t staged here)
    float* beta  = alpha + (size_t)BB * TT * KK;      // 1024

    // Resolve __device__ symbols to real device pointers
    __nv_bfloat16 *xh, *xl, *whp, *wlp;
    float *cv, *cg, *cs;
    cudaGetSymbolAddress((void**)&xh,  g_xh);
    cudaGetSymbolAddress((void**)&xl,  g_xl);
    cudaGetSymbolAddress((void**)&whp, g_wh);
    cudaGetSymbolAddress((void**)&wlp, g_wl);
    cudaGetSymbolAddress((void**)&cv,  g_cv);
    cudaGetSymbolAddress((void**)&cg,  g_cg);
    cudaGetSymbolAddress((void**)&cs,  g_cs);
    cudaFuncSetAttribute(mma_gemm_all, cudaFuncAttributeMaxDynamicSharedMemorySize, MMA_DSMEM);
    cudaFuncSetAttribute(zfused_kernel, cudaFuncAttributeMaxDynamicSharedMemorySize, 76800);

    // 1. split all activations (att|hid|sent) -> bf16 hi/lo
    split_all<<<(ROWS_ALL * HH / 4 + 255) / 256, 256>>>(att, hid, sent, xh, xl);
    // 2. transpose+split all weights
    wsplit_all<<<dim3(16, 16, 3), dim3(32, 8)>>>(Wv, Wg, Ws, whp, wlp);
    // 3. all three GEMMs in one launch (cp.async pipelined)
    mma_gemm_all<<<dim3(4, 65), 256, MMA_DSMEM>>>(xh, xl, whp, wlp, cv, cg, cs);
    // 4. fused z_t + z_ext
    zfused_kernel<<<dim3(49, 32), 256, 75776>>>(wh, alpha);
    // 5. softmax + beta
    softmax_kernel<<<128, 256>>>(alpha, beta);
    // 6. c_t + sentinel blend
    ct_kernel<<<dim3(32, 4), 256>>>(att, sent, alpha, beta, chat);
}

// round 6
// speedup vs baseline: 2.1038x; 1.3942x over previous
#include <cuda_runtime.h>
#include <cuda_bf16.h>
#include <cstdint>
#include <math.h>

// Problem constants
#define BB 32
#define TT 32
#define KK 196
#define HH 512
#define AA 512
#define GK 512

#define ROWS_ATT (BB * KK)          // 6272
#define ROWS_HID (BB * TT)          // 1024
#define ROWS_ALL (ROWS_ATT + 2 * ROWS_HID)   // 8320

// ---------------------------------------------------------------------------
// Scratch (__device__ globals; no cudaMalloc allowed)
__device__ float g_cv[BB * KK * AA];                 // 12.8 MB
__device__ float g_cg[BB * TT * AA];                 // 2 MB
__device__ float g_cs[BB * TT * AA];                 // 2 MB
__device__ float g_zext[BB * TT];
__device__ __nv_bfloat16 g_xh[ROWS_ALL * HH];        // concat activations hi
__device__ __nv_bfloat16 g_xl[ROWS_ALL * HH];        // concat activations lo
__device__ __nv_bfloat16 g_wh[3 * AA * HH];          // W^T hi (Wv, Wg, Ws)
__device__ __nv_bfloat16 g_wl[3 * AA * HH];          // W^T lo

// ---------------------------------------------------------------------------
__device__ __forceinline__ float tanh_mufu(float x) {
    float y;
    asm("tanh.approx.f32 %0, %1;" : "=f"(y) : "f"(x));
    return y;
}
__device__ __forceinline__ float warp_sum(float v) {
    #pragma unroll
    for (int o = 16; o; o >>= 1) v += __shfl_xor_sync(0xffffffffu, v, o);
    return v;
}

// mma.sync m16n8k16 row.col f32.bf16.bf16.f32, D == C
__device__ __forceinline__ void hmma(float* c, const uint32_t* a, const uint32_t* b) {
    asm volatile(
        "mma.sync.aligned.m16n8k16.row.col.f32.bf16.bf16.f32 "
        "{%0,%1,%2,%3}, {%4,%5,%6,%7}, {%8,%9}, {%0,%1,%2,%3};"
        : "+f"(c[0]), "+f"(c[1]), "+f"(c[2]), "+f"(c[3])
        : "r"(a[0]), "r"(a[1]), "r"(a[2]), "r"(a[3]), "r"(b[0]), "r"(b[1]));
}

__device__ __forceinline__ uint32_t smem_u32(const void* p) {
    uint32_t a;
    asm("{ .reg .u64 t; cvta.to.shared.u64 t, %1; cvt.u32.u64 %0, t; }" : "=r"(a) : "l"(p));
    return a;
}
__device__ __forceinline__ void cp16(uint32_t dst, const void* src) {
    asm volatile("cp.async.cg.shared.global [%0], [%1], 16;" :: "r"(dst), "l"(src));
}
#define CP_COMMIT() asm volatile("cp.async.commit_group;" ::: "memory")
#define CP_WAIT1()  asm volatile("cp.async.wait_group 1;" ::: "memory")
#define CP_WAIT0()  asm volatile("cp.async.wait_group 0;" ::: "memory")

// ---------------------------------------------------------------------------
// fp32 -> bf16 hi/lo split; all three activations in one launch.
__global__ void split_all(const float* __restrict__ att, const float* __restrict__ hid,
                          const float* __restrict__ sent,
                          __nv_bfloat16* __restrict__ H, __nv_bfloat16* __restrict__ L) {
    const int N4 = ROWS_ALL * HH / 4;
    int i = blockIdx.x * blockDim.x + threadIdx.x;
    if (i >= N4) return;
    const float4* src;
    int li;
    if (i < ROWS_ATT * 128)            { src = (const float4*)att;  li = i; }
    else if (i < (ROWS_ATT + ROWS_HID) * 128) { src = (const float4*)hid;  li = i - ROWS_ATT * 128; }
    else                               { src = (const float4*)sent; li = i - (ROWS_ATT + ROWS_HID) * 128; }
    float4 v = src[li];
    __nv_bfloat16 h0 = __float2bfloat16(v.x);
    __nv_bfloat16 h1 = __float2bfloat16(v.y);
    __nv_bfloat16 h2 = __float2bfloat16(v.z);
    __nv_bfloat16 h3 = __float2bfloat16(v.w);
    ((__nv_bfloat162*)H)[2 * i]     = __nv_bfloat162(h0, h1);
    ((__nv_bfloat162*)H)[2 * i + 1] = __nv_bfloat162(h2, h3);
    ((__nv_bfloat162*)L)[2 * i]     = __nv_bfloat162(__float2bfloat16(v.x - __bfloat162float(h0)),
                                                     __float2bfloat16(v.y - __bfloat162float(h1)));
    ((__nv_bfloat162*)L)[2 * i + 1] = __nv_bfloat162(__float2bfloat16(v.z - __bfloat162float(h2)),
                                                     __float2bfloat16(v.w - __bfloat162float(h3)));
}

// W[h][a] -> W^T[a][h], hi/lo split, 3 weights via blockIdx.z
__global__ void wsplit_all(const float* __restrict__ Wv, const float* __restrict__ Wg,
                           const float* __restrict__ Ws,
                           __nv_bfloat16* __restrict__ Ht, __nv_bfloat16* __restrict__ Lt) {
    __shared__ float t[32][33];
    int z = blockIdx.z;
    const float* W = (z == 0) ? Wv : (z == 1) ? Wg : Ws;
    size_t wo = (size_t)z * AA * HH;
    int a0 = blockIdx.x * 32, h0 = blockIdx.y * 32;
    int tx = threadIdx.x, ty = threadIdx.y;
    #pragma unroll
    for (int r = ty; r < 32; r += 8)
        t[r][tx] = W[(size_t)(h0 + r) * AA + a0 + tx];
    __syncthreads();
    #pragma unroll
    for (int r = ty; r < 32; r += 8) {
        float v = t[tx][r];
        __nv_bfloat16 hh = __float2bfloat16(v);
        Ht[wo + (size_t)(a0 + r) * HH + h0 + tx] = hh;
        Lt[wo + (size_t)(a0 + r) * HH + h0 + tx] = __float2bfloat16(v - __bfloat162float(hh));
    }
}

// ---------------------------------------------------------------------------
// Merged bf16x3 tensor GEMM, cp.async 2-stage pipeline (unchanged from R5).
#define SROW 40
#define TILE_E (128 * SROW)
#define TILE_B (TILE_E * 2)
#define MMA_DSMEM (TILE_B * 4 * 2)       // 81920

__global__ void __launch_bounds__(256) mma_gemm_all(
        const __nv_bfloat16* __restrict__ Xh, const __nv_bfloat16* __restrict__ Xl,
        const __nv_bfloat16* __restrict__ Wh, const __nv_bfloat16* __restrict__ Wl,
        float* __restrict__ cv, float* __restrict__ cg, float* __restrict__ cs) {
    extern __shared__ __nv_bfloat16 dynsm[];
    uint32_t sb = smem_u32(dynsm);

    int tid = threadIdx.x, wid = tid >> 5, lane = tid & 31;
    int wm = wid >> 2, wn = wid & 3;
    int g = lane >> 2, tig = lane & 3;
    int my = blockIdx.y;
    int n0 = blockIdx.x * 128;

    int arow0; size_t wo; float* C; int crow0;
    if (my < 49)      { arow0 = my * 128;                    wo = 0;                      C = cv; crow0 = my * 128; }
    else if (my < 57) { arow0 = ROWS_ATT + (my - 49) * 128;  wo = (size_t)AA * HH;        C = cg; crow0 = (my - 49) * 128; }
    else              { arow0 = ROWS_ATT + ROWS_HID + (my - 57) * 128; wo = 2 * (size_t)AA * HH; C = cs; crow0 = (my - 57) * 128; }

    float acc[4][4][4];
    #pragma unroll
    for (int i = 0; i < 4; i++)
        #pragma unroll
        for (int j = 0; j < 4; j++)
            #pragma unroll
            for (int q = 0; q < 4; q++) acc[i][j][q] = 0.0f;

    int lr = tid >> 2, lc = (tid & 3) * 8;

    auto load_stage = [&](int s, int k0) {
        uint32_t base = sb + (uint32_t)(s * 4) * TILE_B;
        #pragma unroll
        for (int p = 0; p < 2; p++) {
            int r = lr + 64 * p;
            uint32_t soff = (uint32_t)(r * SROW + lc) * 2;
            cp16(base + 0 * TILE_B + soff, Xh + (size_t)(arow0 + r) * GK + k0 + lc);
            cp16(base + 1 * TILE_B + soff, Xl + (size_t)(arow0 + r) * GK + k0 + lc);
            cp16(base + 2 * TILE_B + soff, Wh + wo + (size_t)(n0 + r) * HH + k0 + lc);
            cp16(base + 3 * TILE_B + soff, Wl + wo + (size_t)(n0 + r) * HH + k0 + lc);
        }
    };

    load_stage(0, 0);
    CP_COMMIT();

    const int NIT = GK / 32;
    for (int it = 0; it < NIT; it++) {
        if (it + 1 < NIT) {
            load_stage((it + 1) & 1, (it + 1) * 32);
            CP_COMMIT();
            CP_WAIT1();
        } else {
            CP_WAIT0();
        }
        __syncthreads();

        const __nv_bfloat16* sAh = dynsm + (size_t)((it & 1) * 4 + 0) * TILE_E;
        const __nv_bfloat16* sAl = dynsm + (size_t)((it & 1) * 4 + 1) * TILE_E;
        const __nv_bfloat16* sBh = dynsm + (size_t)((it & 1) * 4 + 2) * TILE_E;
        const __nv_bfloat16* sBl = dynsm + (size_t)((it & 1) * 4 + 3) * TILE_E;

        #pragma unroll
        for (int ks = 0; ks < 2; ks++) {
            int c0 = ks * 16 + 2 * tig;
            uint32_t aH[4][4], aL[4][4], bH[4][2], bL[4][2];
            #pragma unroll
            for (int mf = 0; mf < 4; mf++) {
                int mr = wm * 64 + mf * 16;
                aH[mf][0] = *(const uint32_t*)&sAh[(mr + g) * SROW + c0];
                aH[mf][1] = *(const uint32_t*)&sAh[(mr + g + 8) * SROW + c0];
                aH[mf][2] = *(const uint32_t*)&sAh[(mr + g) * SROW + c0 + 8];
                aH[mf][3] = *(const uint32_t*)&sAh[(mr + g + 8) * SROW + c0 + 8];
                aL[mf][0] = *(const uint32_t*)&sAl[(mr + g) * SROW + c0];
                aL[mf][1] = *(const uint32_t*)&sAl[(mr + g + 8) * SROW + c0];
                aL[mf][2] = *(const uint32_t*)&sAl[(mr + g) * SROW + c0 + 8];
                aL[mf][3] = *(const uint32_t*)&sAl[(mr + g + 8) * SROW + c0 + 8];
            }
            #pragma unroll
            for (int nf = 0; nf < 4; nf++) {
                int nr = wn * 32 + nf * 8;
                bH[nf][0] = *(const uint32_t*)&sBh[(nr + g) * SROW + c0];
                bH[nf][1] = *(const uint32_t*)&sBh[(nr + g) * SROW + c0 + 8];
                bL[nf][0] = *(const uint32_t*)&sBl[(nr + g) * SROW + c0];
                bL[nf][1] = *(const uint32_t*)&sBl[(nr + g) * SROW + c0 + 8];
            }
            #pragma unroll
            for (int mf = 0; mf < 4; mf++)
                #pragma unroll
                for (int nf = 0; nf < 4; nf++) hmma(acc[mf][nf], aH[mf], bH[nf]);
            #pragma unroll
            for (int mf = 0; mf < 4; mf++)
                #pragma unroll
                for (int nf = 0; nf < 4; nf++) hmma(acc[mf][nf], aH[mf], bL[nf]);
            #pragma unroll
            for (int mf = 0; mf < 4; mf++)
                #pragma unroll
                for (int nf = 0; nf < 4; nf++) hmma(acc[mf][nf], aL[mf], bH[nf]);
        }
        __syncthreads();
    }

    #pragma unroll
    for (int mf = 0; mf < 4; mf++) {
        int row = crow0 + wm * 64 + mf * 16 + g;
        #pragma unroll
        for (int nf = 0; nf < 4; nf++) {
            int col = n0 + wn * 32 + nf * 8 + 2 * tig;
            *(float2*)&C[(size_t)row * AA + col] =
                make_float2(acc[mf][nf][0], acc[mf][nf][1]);
            *(float2*)&C[(size_t)(row + 8) * AA + col] =
                make_float2(acc[mf][nf][2], acc[mf][nf][3]);
        }
    }
}

// ---------------------------------------------------------------------------
// zfused v2: high-occupancy, register-resident cg/wh.
// grid (KTILES=14, 4, 32), block 256 (8 warps). Warp w handles t = tg*8+w.
// Block loads cv tile [14 k][512] to smem; inner loop = 1 LDS + FADD + MUFU + FFMA.
// kt==0 blocks also compute zext from cs (LDG).
#define KT 14
#define KTILES (KK / KT)   // 14

__global__ void __launch_bounds__(256) zfused_kernel(const float* __restrict__ wh,
                                                     float* __restrict__ zout) {
    __shared__ float s_cv[KT * 512];   // 28672 B
    __shared__ float s_wh[512];

    int kt = blockIdx.x, tg = blockIdx.y, b = blockIdx.z;
    int tid = threadIdx.x, wid = tid >> 5, lane = tid & 31;
    int t = tg * 8 + wid;
    int row = b * TT + t;

    const float* cvp = g_cv + ((size_t)b * KK + kt * KT) * AA;
    #pragma unroll
    for (int i = tid * 4; i < KT * 512; i += 1024)
        *(float4*)&s_cv[i] = *(const float4*)(cvp + i);
    if (tid * 4 < 512)
        *(float4*)&s_wh[tid * 4] = *(const float4*)(wh + tid * 4);
    __syncthreads();

    // register-resident cg row and wh
    float cgr[16], whr[16];
    const float* cgp = g_cg + (size_t)row * AA;
    #pragma unroll
    for (int j = 0; j < 16; j++) {
        cgr[j] = cgp[lane + 32 * j];
        whr[j] = s_wh[lane + 32 * j];
    }

    #pragma unroll
    for (int kk = 0; kk < KT; kk++) {
        const float* cvk = &s_cv[kk * 512];
        float a0 = 0.0f, a1 = 0.0f;
        #pragma unroll
        for (int j = 0; j < 16; j += 2) {
            a0 = fmaf(whr[j],     tanh_mufu(cvk[lane + 32 * j]       + cgr[j]),     a0);
            a1 = fmaf(whr[j + 1], tanh_mufu(cvk[lane + 32 * (j + 1)] + cgr[j + 1]), a1);
        }
        float acc = warp_sum(a0 + a1);
        if (lane == 0)
            zout[(size_t)row * KK + kt * KT + kk] = acc;
    }

    // sentinel z_ext (once per row, on kt==0 blocks)
    if (kt == 0) {
        const float* cst = g_cs + (size_t)row * AA;
        float a0 = 0.0f, a1 = 0.0f;
        #pragma unroll
        for (int j = 0; j < 16; j += 2) {
            a0 = fmaf(whr[j],     tanh_mufu(cst[lane + 32 * j]       + cgr[j]),     a0);
            a1 = fmaf(whr[j + 1], tanh_mufu(cst[lane + 32 * (j + 1)] + cgr[j + 1]), a1);
        }
        float acc = warp_sum(a0 + a1);
        if (lane == 0) g_zext[row] = acc;
    }
}

// ---------------------------------------------------------------------------
// Softmax over K=196 + beta; one warp per (b,t) row
__global__ void softmax_kernel(float* __restrict__ z, float* __restrict__ beta) {
    const float L2E = 1.4426950408889634f;
    int wid = threadIdx.x >> 5, lane = threadIdx.x & 31;
    int row = blockIdx.x * 8 + wid;
    float* zr = z + (size_t)row * KK;

    float v[7];
    float m = -INFINITY;
    #pragma unroll
    for (int j = 0; j < 7; j++) {
        int k = lane + 32 * j;
        v[j] = (k < KK) ? zr[k] : -INFINITY;
        m = fmaxf(m, v[j]);
    }
    #pragma unroll
    for (int o = 16; o; o >>= 1) m = fmaxf(m, __shfl_xor_sync(0xffffffffu, m, o));

    float s = 0.0f;
    #pragma unroll
    for (int j = 0; j < 7; j++) {
        float e = exp2f((v[j] - m) * L2E);
        v[j] = e;
        s += e;
    }
    s = warp_sum(s);

    float inv = __fdividef(1.0f, s);
    #pragma unroll
    for (int j = 0; j < 7; j++) {
        int k = lane + 32 * j;
        if (k < KK) zr[k] = v[j] * inv;
    }

    if (lane == 0) {
        float ze = g_zext[row];
        float m2 = fmaxf(m, ze);
        float ee = exp2f((ze - m2) * L2E);
        float s2 = s * exp2f((m - m2) * L2E) + ee;
        beta[row] = __fdividef(ee, s2);
    }
}

// ---------------------------------------------------------------------------
// c_hat[b,t,:] = beta*sentinel + (1-beta) * sum_k alpha[b,t,k]*att_feats[b,k,:]
__global__ void ct_kernel(const float* __restrict__ af, const float* __restrict__ sent,
                          const float* __restrict__ alpha, const float* __restrict__ beta,
                          float* __restrict__ chat) {
    __shared__ float s_alpha[8][KK];
    __shared__ float s_beta[8];
    int b = blockIdx.x, tg = blockIdx.y;
    int tid = threadIdx.x;
    int trow0 = b * TT + tg * 8;

    for (int i = tid; i < 8 * KK; i += 256)
        s_alpha[i / KK][i % KK] = alpha[(size_t)(trow0 + i / KK) * KK + i % KK];
    if (tid < 8) s_beta[tid] = beta[trow0 + tid];
    __syncthreads();

    float acc[8][2];
    #pragma unroll
    for (int t = 0; t < 8; t++) { acc[t][0] = 0.0f; acc[t][1] = 0.0f; }

    const float* afb = af + (size_t)b * KK * HH;
    int h2 = tid * 2;
    for (int k = 0; k < KK; k++) {
        float2 vv = *(const float2*)(afb + (size_t)k * HH + h2);
        #pragma unroll
        for (int t = 0; t < 8; t++) {
            float al = s_alpha[t][k];
            acc[t][0] = fmaf(al, vv.x, acc[t][0]);
            acc[t][1] = fmaf(al, vv.y, acc[t][1]);
        }
    }

    #pragma unroll
    for (int t = 0; t < 8; t++) {
        float be = s_beta[t];
        float om = 1.0f - be;
        size_t row = (size_t)(trow0 + t);
        float2 sv = *(const float2*)(sent + row * HH + h2);
        float2 o;
        o.x = be * sv.x + om * acc[t][0];
        o.y = be * sv.y + om * acc[t][1];
        *(float2*)(chat + row * HH + h2) = o;
    }
}

// ---------------------------------------------------------------------------
extern "C" void kernel_launch(void* const* d_in, const int* in_sizes, int n_in,
                              void* d_out, int out_size) {
    const float* att  = (const float*)d_in[0];
    const float* hid  = (const float*)d_in[1];
    const float* sent = (const float*)d_in[2];
    const float* Wv   = (const float*)d_in[3];
    const float* Wg   = (const float*)d_in[4];
    const float* Ws   = (const float*)d_in[5];
    const float* wh   = (const float*)d_in[6];

    float* out   = (float*)d_out;
    float* chat  = out;                               // 524288
    float* alpha = out + (size_t)BB * TT * HH;        // 200704 (z_t staged here)
    float* beta  = alpha + (size_t)BB * TT * KK;      // 1024

    __nv_bfloat16 *xh, *xl, *whp, *wlp;
    float *cv, *cg, *cs;
    cudaGetSymbolAddress((void**)&xh,  g_xh);
    cudaGetSymbolAddress((void**)&xl,  g_xl);
    cudaGetSymbolAddress((void**)&whp, g_wh);
    cudaGetSymbolAddress((void**)&wlp, g_wl);
    cudaGetSymbolAddress((void**)&cv,  g_cv);
    cudaGetSymbolAddress((void**)&cg,  g_cg);
    cudaGetSymbolAddress((void**)&cs,  g_cs);
    cudaFuncSetAttribute(mma_gemm_all, cudaFuncAttributeMaxDynamicSharedMemorySize, MMA_DSMEM);

    // 1. split all activations (att|hid|sent) -> bf16 hi/lo
    split_all<<<(ROWS_ALL * HH / 4 + 255) / 256, 256>>>(att, hid, sent, xh, xl);
    // 2. transpose+split all weights
    wsplit_all<<<dim3(16, 16, 3), dim3(32, 8)>>>(Wv, Wg, Ws, whp, wlp);
    // 3. all three GEMMs in one launch (cp.async pipelined)
    mma_gemm_all<<<dim3(4, 65), 256, MMA_DSMEM>>>(xh, xl, whp, wlp, cv, cg, cs);
    // 4. fused z_t + z_ext (high-occupancy v2)
    zfused_kernel<<<dim3(KTILES, 4, 32), 256>>>(wh, alpha);
    // 5. softmax + beta
    softmax_kernel<<<128, 256>>>(alpha, beta);
    // 6. c_t + sentinel blend
    ct_kernel<<<dim3(32, 4), 256>>>(att, sent, alpha, beta, chat);
}